// round 1
// baseline (speedup 1.0000x reference)
#include <cuda_runtime.h>
#include <math.h>

// Problem shape (fixed by the dataset; runtime-checked against in_sizes)
#define NNODES 100000
#define EDGES  3200000
#define HDIM   128
#define EDIM   16
#define PTYPES 6

// Scratch (no allocations allowed in kernel_launch) — __device__ globals.
__device__ float g_e0[EDGES];       // exp(s0) per edge     (12.8 MB)
__device__ float g_denom0[NNODES];  // sum exp(s0) per row
__device__ float g_denom1[NNODES];  // sum exp(s1) per row
__device__ float g_pexp[PTYPES];    // exp(path_emb_w[p])
__device__ float g_expl;            // exp(lambda0)

// ---------------------------------------------------------------------------
// Kernel 0: zero output + denominators, precompute exp tables.
// ---------------------------------------------------------------------------
__global__ void k_init(float* __restrict__ out,
                       const float* __restrict__ lambda0,
                       const float* __restrict__ path_w,
                       int n_nodes) {
    int tid    = blockIdx.x * blockDim.x + threadIdx.x;
    int stride = gridDim.x * blockDim.x;

    int total4 = n_nodes * (HDIM / 4);
    float4 z = make_float4(0.f, 0.f, 0.f, 0.f);
    for (int i = tid; i < total4; i += stride)
        reinterpret_cast<float4*>(out)[i] = z;

    for (int i = tid; i < n_nodes; i += stride) {
        g_denom0[i] = 0.f;
        g_denom1[i] = 0.f;
    }

    if (tid < PTYPES) g_pexp[tid] = expf(path_w[tid]);
    if (tid == 0)     g_expl     = expf(lambda0[0]);
}

// ---------------------------------------------------------------------------
// Kernel 1: one warp per edge.
//   s0 = (q[row].k[col]) / sqrt(H) + exp(lambda0) * (eigs[row].eigs[col])
//   e0 = exp(s0)   (no max-subtraction: cancels exactly in the softmax ratio,
//                   and s0 magnitudes are far inside fp32 exp range)
//   denom0[row] += e0 ;  denom1[row] += exp(path_w[ptype])
// ---------------------------------------------------------------------------
__global__ void k_pass1(const float* __restrict__ q,
                        const float* __restrict__ k,
                        const float* __restrict__ eigs,
                        const int*   __restrict__ indices,
                        const int*   __restrict__ ptype,
                        int n_edges) {
    int gw   = (blockIdx.x * blockDim.x + threadIdx.x) >> 5;
    int lane = threadIdx.x & 31;
    if (gw >= n_edges) return;

    const int e   = gw;
    const int row = __ldg(indices + e);
    const int col = __ldg(indices + n_edges + e);

    // 128-dim dot: one float4 per lane
    float4 a = __ldg(reinterpret_cast<const float4*>(q + (size_t)row * HDIM) + lane);
    float4 b = __ldg(reinterpret_cast<const float4*>(k + (size_t)col * HDIM) + lane);
    float x  = a.x * b.x + a.y * b.y + a.z * b.z + a.w * b.w;

    // 16-dim eig dot on lanes 0..15
    float y = 0.f;
    if (lane < EDIM) {
        float er = __ldg(eigs + (size_t)row * EDIM + lane);
        float ec = __ldg(eigs + (size_t)col * EDIM + lane);
        y = er * ec;
    }

    #pragma unroll
    for (int o = 16; o > 0; o >>= 1) {
        x += __shfl_xor_sync(0xffffffffu, x, o);
        y += __shfl_xor_sync(0xffffffffu, y, o);
    }

    if (lane == 0) {
        const float inv_sqrt_h = 0.08838834764831845f;  // 1/sqrt(128)
        float s0 = x * inv_sqrt_h + g_expl * y;
        float e0 = expf(s0);
        g_e0[e] = e0;
        atomicAdd(g_denom0 + row, e0);
        atomicAdd(g_denom1 + row, g_pexp[__ldg(ptype + e)]);
    }
}

// ---------------------------------------------------------------------------
// Kernel 2: one warp per edge. Scatter w * v[col] into out[row] with
// vectorized reductions (red.global.add.v4.f32 — 32 ops/edge vs 128 scalar).
// ---------------------------------------------------------------------------
__device__ __forceinline__ void red_add_v4(float* addr, float a, float b,
                                           float c, float d) {
    asm volatile("red.global.add.v4.f32 [%0], {%1, %2, %3, %4};"
                 :: "l"(addr), "f"(a), "f"(b), "f"(c), "f"(d)
                 : "memory");
}

__global__ void k_pass2(const float* __restrict__ v,
                        const int*   __restrict__ indices,
                        const int*   __restrict__ ptype,
                        float* __restrict__ out,
                        int n_edges) {
    int gw   = (blockIdx.x * blockDim.x + threadIdx.x) >> 5;
    int lane = threadIdx.x & 31;
    if (gw >= n_edges) return;

    const int e   = gw;
    const int row = __ldg(indices + e);
    const int col = __ldg(indices + n_edges + e);

    float w;
    if (lane == 0) {
        float e0 = g_e0[e];
        float d0 = g_denom0[row];
        float d1 = g_denom1[row];
        float e1 = g_pexp[__ldg(ptype + e)];
        w = 0.5f * (e0 / d0 + e1 / d1);
    }
    w = __shfl_sync(0xffffffffu, w, 0);

    float4 vv = __ldg(reinterpret_cast<const float4*>(v + (size_t)col * HDIM) + lane);
    float* dst = out + (size_t)row * HDIM + lane * 4;
    red_add_v4(dst, w * vv.x, w * vv.y, w * vv.z, w * vv.w);
}

// ---------------------------------------------------------------------------
// Launch
// Inputs (metadata order): 0 q[N,H] 1 k[N,H] 2 v[N,H] 3 eigs[N,ED]
//                          4 lambda0[1] 5 path_emb_w[P,1]
//                          6 indices[2,E] 7 path_type[E]
// Output: float32 [N, H]
// ---------------------------------------------------------------------------
extern "C" void kernel_launch(void* const* d_in, const int* in_sizes, int n_in,
                              void* d_out, int out_size) {
    const float* q       = (const float*)d_in[0];
    const float* k       = (const float*)d_in[1];
    const float* v       = (const float*)d_in[2];
    const float* eigs    = (const float*)d_in[3];
    const float* lambda0 = (const float*)d_in[4];
    const float* path_w  = (const float*)d_in[5];
    const int*   indices = (const int*)d_in[6];
    const int*   ptype   = (const int*)d_in[7];
    float*       out     = (float*)d_out;

    int n_edges = in_sizes[6] / 2;
    int n_nodes = in_sizes[0] / HDIM;
    if (n_edges > EDGES) n_edges = EDGES;  // scratch bound (dataset: exactly EDGES)

    k_init<<<2048, 256>>>(out, lambda0, path_w, n_nodes);

    // one warp per edge, 8 warps per block
    int blocks = (n_edges + 7) / 8;
    k_pass1<<<blocks, 256>>>(q, k, eigs, indices, ptype, n_edges);
    k_pass2<<<blocks, 256>>>(v, indices, ptype, out, n_edges);
}

// round 2
// speedup vs baseline: 1.8472x; 1.8472x over previous
#include <cuda_runtime.h>
#include <math.h>

#define NNODES 100000
#define EDGES  3200000
#define HDIM   128
#define EDIM   16
#define PTYPES 6

// ---- __device__ scratch (allocations are banned) ----
__device__ int   g_cnt[NNODES];        // degree histogram
__device__ int   g_rowptr[NNODES + 1]; // CSR row pointers
__device__ int   g_rowpos[NNODES];     // scatter cursors
__device__ int   g_col_s[EDGES];       // CSR-ordered col index
__device__ float g_pw_s[EDGES];        // CSR-ordered exp(path_w[ptype])
__device__ float g_e0[EDGES];          // CSR-ordered exp(s0)
__device__ float g_d0[NNODES];         // sum exp(s0) per row
__device__ float g_d1[NNODES];         // sum exp(s1) per row
__device__ float g_pexp[PTYPES];
__device__ float g_expl;

// ---------------------------------------------------------------------------
// 0) init: zero histogram, precompute exp tables
// ---------------------------------------------------------------------------
__global__ void k_init(const float* __restrict__ lambda0,
                       const float* __restrict__ path_w, int n_nodes) {
    int tid = blockIdx.x * blockDim.x + threadIdx.x;
    int stride = gridDim.x * blockDim.x;
    for (int i = tid; i < n_nodes; i += stride) g_cnt[i] = 0;
    if (tid < PTYPES) g_pexp[tid] = expf(path_w[tid]);
    if (tid == 0)     g_expl = expf(lambda0[0]);
}

// ---------------------------------------------------------------------------
// 1) histogram of destination rows
// ---------------------------------------------------------------------------
__global__ void k_hist(const int* __restrict__ indices, int n_edges) {
    int e = blockIdx.x * blockDim.x + threadIdx.x;
    if (e < n_edges) atomicAdd(&g_cnt[__ldg(indices + e)], 1);
}

// ---------------------------------------------------------------------------
// 2) exclusive scan (single block, 1024 threads over 100k counters)
// ---------------------------------------------------------------------------
__global__ void k_scan(int n) {
    __shared__ int part[1024];
    int tid = threadIdx.x;
    int chunk = (n + 1023) / 1024;
    int start = tid * chunk;
    int end   = min(start + chunk, n);
    int s = 0;
    for (int i = start; i < end; i++) s += g_cnt[i];
    part[tid] = s;
    __syncthreads();
    for (int off = 1; off < 1024; off <<= 1) {
        int v = 0;
        if (tid >= off) v = part[tid - off];
        __syncthreads();
        if (tid >= off) part[tid] += v;
        __syncthreads();
    }
    int run = (tid == 0) ? 0 : part[tid - 1];
    for (int i = start; i < end; i++) {
        g_rowptr[i] = run;
        g_rowpos[i] = run;
        run += g_cnt[i];
    }
    if (end == n && start <= n) g_rowptr[n] = run;
}

// ---------------------------------------------------------------------------
// 3) scatter edges into CSR order (col + precomputed path weight)
// ---------------------------------------------------------------------------
__global__ void k_scatter(const int* __restrict__ indices,
                          const int* __restrict__ ptype, int n_edges) {
    int e = blockIdx.x * blockDim.x + threadIdx.x;
    if (e >= n_edges) return;
    int row = __ldg(indices + e);
    int col = __ldg(indices + n_edges + e);
    int pos = atomicAdd(&g_rowpos[row], 1);
    g_col_s[pos] = col;
    g_pw_s[pos]  = g_pexp[__ldg(ptype + e)];
}

// ---------------------------------------------------------------------------
// 4) pass1: warp per row. q[row]/eigs[row] resident in registers.
//    e0 = exp(q.k/sqrt(H) + exp(l0)*eig.eig); accumulate denominators.
//    (segment-max cancels exactly in the softmax ratio; fp32 exp is safe here)
// ---------------------------------------------------------------------------
__global__ void k_pass1(const float* __restrict__ q,
                        const float* __restrict__ k,
                        const float* __restrict__ eigs, int n_nodes) {
    int warp = (blockIdx.x * blockDim.x + threadIdx.x) >> 5;
    int lane = threadIdx.x & 31;
    if (warp >= n_nodes) return;
    const int row = warp;
    const int beg = g_rowptr[row];
    const int end = g_rowptr[row + 1];
    if (beg == end) return;

    float4 qv = __ldg(reinterpret_cast<const float4*>(q + (size_t)row * HDIM) + lane);
    float  er = (lane < EDIM) ? __ldg(eigs + (size_t)row * EDIM + lane) : 0.f;
    const float expl = g_expl;
    const float inv_sqrt_h = 0.08838834764831845f;

    float d0 = 0.f, d1 = 0.f;
    int j = beg;
    for (; j + 2 <= end; j += 2) {
        int c0 = __ldg(g_col_s + j);
        int c1 = __ldg(g_col_s + j + 1);
        float4 k0 = __ldg(reinterpret_cast<const float4*>(k + (size_t)c0 * HDIM) + lane);
        float4 k1 = __ldg(reinterpret_cast<const float4*>(k + (size_t)c1 * HDIM) + lane);
        float ec0 = (lane < EDIM) ? __ldg(eigs + (size_t)c0 * EDIM + lane) : 0.f;
        float ec1 = (lane < EDIM) ? __ldg(eigs + (size_t)c1 * EDIM + lane) : 0.f;
        float x0 = qv.x * k0.x + qv.y * k0.y + qv.z * k0.z + qv.w * k0.w;
        float x1 = qv.x * k1.x + qv.y * k1.y + qv.z * k1.z + qv.w * k1.w;
        float y0 = er * ec0;
        float y1 = er * ec1;
        #pragma unroll
        for (int o = 16; o > 0; o >>= 1) {
            x0 += __shfl_xor_sync(0xffffffffu, x0, o);
            x1 += __shfl_xor_sync(0xffffffffu, x1, o);
            y0 += __shfl_xor_sync(0xffffffffu, y0, o);
            y1 += __shfl_xor_sync(0xffffffffu, y1, o);
        }
        float e0 = expf(x0 * inv_sqrt_h + expl * y0);
        float e1 = expf(x1 * inv_sqrt_h + expl * y1);
        d0 += e0 + e1;
        d1 += __ldg(g_pw_s + j) + __ldg(g_pw_s + j + 1);
        if (lane == 0) { g_e0[j] = e0; g_e0[j + 1] = e1; }
    }
    if (j < end) {
        int c0 = __ldg(g_col_s + j);
        float4 k0 = __ldg(reinterpret_cast<const float4*>(k + (size_t)c0 * HDIM) + lane);
        float ec0 = (lane < EDIM) ? __ldg(eigs + (size_t)c0 * EDIM + lane) : 0.f;
        float x0 = qv.x * k0.x + qv.y * k0.y + qv.z * k0.z + qv.w * k0.w;
        float y0 = er * ec0;
        #pragma unroll
        for (int o = 16; o > 0; o >>= 1) {
            x0 += __shfl_xor_sync(0xffffffffu, x0, o);
            y0 += __shfl_xor_sync(0xffffffffu, y0, o);
        }
        float e0 = expf(x0 * inv_sqrt_h + expl * y0);
        d0 += e0;
        d1 += __ldg(g_pw_s + j);
        if (lane == 0) g_e0[j] = e0;
    }
    if (lane == 0) { g_d0[row] = d0; g_d1[row] = d1; }
}

// ---------------------------------------------------------------------------
// 5) pass2: warp per row. Register accumulation, one clean 512B store/row.
// ---------------------------------------------------------------------------
__global__ void k_pass2(const float* __restrict__ v,
                        float* __restrict__ out, int n_nodes) {
    int warp = (blockIdx.x * blockDim.x + threadIdx.x) >> 5;
    int lane = threadIdx.x & 31;
    if (warp >= n_nodes) return;
    const int row = warp;
    const int beg = g_rowptr[row];
    const int end = g_rowptr[row + 1];

    float4 acc = make_float4(0.f, 0.f, 0.f, 0.f);
    if (beg < end) {
        const float i0 = 0.5f / g_d0[row];
        const float i1 = 0.5f / g_d1[row];
        int j = beg;
        for (; j + 2 <= end; j += 2) {
            float w0 = __ldg(g_e0 + j)     * i0 + __ldg(g_pw_s + j)     * i1;
            float w1 = __ldg(g_e0 + j + 1) * i0 + __ldg(g_pw_s + j + 1) * i1;
            int c0 = __ldg(g_col_s + j);
            int c1 = __ldg(g_col_s + j + 1);
            float4 v0 = __ldg(reinterpret_cast<const float4*>(v + (size_t)c0 * HDIM) + lane);
            float4 v1 = __ldg(reinterpret_cast<const float4*>(v + (size_t)c1 * HDIM) + lane);
            acc.x += w0 * v0.x + w1 * v1.x;
            acc.y += w0 * v0.y + w1 * v1.y;
            acc.z += w0 * v0.z + w1 * v1.z;
            acc.w += w0 * v0.w + w1 * v1.w;
        }
        if (j < end) {
            float w0 = __ldg(g_e0 + j) * i0 + __ldg(g_pw_s + j) * i1;
            int c0 = __ldg(g_col_s + j);
            float4 v0 = __ldg(reinterpret_cast<const float4*>(v + (size_t)c0 * HDIM) + lane);
            acc.x += w0 * v0.x; acc.y += w0 * v0.y;
            acc.z += w0 * v0.z; acc.w += w0 * v0.w;
        }
    }
    reinterpret_cast<float4*>(out + (size_t)row * HDIM)[lane] = acc;
}

// ---------------------------------------------------------------------------
extern "C" void kernel_launch(void* const* d_in, const int* in_sizes, int n_in,
                              void* d_out, int out_size) {
    const float* q       = (const float*)d_in[0];
    const float* k       = (const float*)d_in[1];
    const float* v       = (const float*)d_in[2];
    const float* eigs    = (const float*)d_in[3];
    const float* lambda0 = (const float*)d_in[4];
    const float* path_w  = (const float*)d_in[5];
    const int*   indices = (const int*)d_in[6];
    const int*   ptype   = (const int*)d_in[7];
    float*       out     = (float*)d_out;

    int n_edges = in_sizes[6] / 2;
    int n_nodes = in_sizes[0] / HDIM;
    if (n_edges > EDGES)  n_edges = EDGES;
    if (n_nodes > NNODES) n_nodes = NNODES;

    int eb = (n_edges + 255) / 256;
    int rb = (n_nodes * 32 + 255) / 256;

    k_init<<<512, 256>>>(lambda0, path_w, n_nodes);
    k_hist<<<eb, 256>>>(indices, n_edges);
    k_scan<<<1, 1024>>>(n_nodes);
    k_scatter<<<eb, 256>>>(indices, ptype, n_edges);
    k_pass1<<<rb, 256>>>(q, k, eigs, n_nodes);
    k_pass2<<<rb, 256>>>(v, out, n_nodes);
}

// round 3
// speedup vs baseline: 2.1899x; 1.1855x over previous
#include <cuda_runtime.h>
#include <math.h>

#define NNODES 100000
#define EDGES  3200000
#define HDIM   128
#define EDIM   16
#define PTYPES 6

// ---- __device__ scratch (allocations are banned) ----
__device__ int   g_cnt[NNODES];        // degree histogram
__device__ int   g_rowptr[NNODES + 1]; // CSR row pointers
__device__ int   g_rowpos[NNODES];     // scatter cursors
__device__ int   g_col_s[EDGES];       // CSR-ordered packed (col | ptype<<24)
__device__ float g_pexp[PTYPES];       // exp(path_emb_w[p])
__device__ float g_expl;               // exp(lambda0)

// ---------------------------------------------------------------------------
// 0) init: zero histogram, precompute exp tables
// ---------------------------------------------------------------------------
__global__ void k_init(const float* __restrict__ lambda0,
                       const float* __restrict__ path_w, int n_nodes) {
    int tid = blockIdx.x * blockDim.x + threadIdx.x;
    int stride = gridDim.x * blockDim.x;
    for (int i = tid; i < n_nodes; i += stride) g_cnt[i] = 0;
    if (tid < PTYPES) g_pexp[tid] = expf(path_w[tid]);
    if (tid == 0)     g_expl = expf(lambda0[0]);
}

// ---------------------------------------------------------------------------
// 1) histogram of destination rows
// ---------------------------------------------------------------------------
__global__ void k_hist(const int* __restrict__ indices, int n_edges) {
    int e = blockIdx.x * blockDim.x + threadIdx.x;
    if (e < n_edges) atomicAdd(&g_cnt[__ldg(indices + e)], 1);
}

// ---------------------------------------------------------------------------
// 2) exclusive scan (single block, 1024 threads over 100k counters)
// ---------------------------------------------------------------------------
__global__ void k_scan(int n) {
    __shared__ int part[1024];
    int tid = threadIdx.x;
    int chunk = (n + 1023) / 1024;
    int start = tid * chunk;
    int end   = min(start + chunk, n);
    int s = 0;
    for (int i = start; i < end; i++) s += g_cnt[i];
    part[tid] = s;
    __syncthreads();
    for (int off = 1; off < 1024; off <<= 1) {
        int v = 0;
        if (tid >= off) v = part[tid - off];
        __syncthreads();
        if (tid >= off) part[tid] += v;
        __syncthreads();
    }
    int run = (tid == 0) ? 0 : part[tid - 1];
    for (int i = start; i < end; i++) {
        g_rowptr[i] = run;
        g_rowpos[i] = run;
        run += g_cnt[i];
    }
    if (end == n && start <= n) g_rowptr[n] = run;
}

// ---------------------------------------------------------------------------
// 3) scatter edges into CSR order — single packed 4B write per edge
// ---------------------------------------------------------------------------
__global__ void k_scatter(const int* __restrict__ indices,
                          const int* __restrict__ ptype, int n_edges) {
    int e = blockIdx.x * blockDim.x + threadIdx.x;
    if (e >= n_edges) return;
    int row = __ldg(indices + e);
    int col = __ldg(indices + n_edges + e);
    int pt  = __ldg(ptype + e);
    int pos = atomicAdd(&g_rowpos[row], 1);
    g_col_s[pos] = col | (pt << 24);
}

// ---------------------------------------------------------------------------
// 4) fused pass: warp per row, single sweep over the row's edges.
//    out[row] = (0.5/d0) * sum_j e0_j v_j + (0.5/d1) * sum_j pw_j v_j
//    (segment-max cancels exactly in the softmax ratio; fp32 exp is safe)
// ---------------------------------------------------------------------------
__global__ void k_fused(const float* __restrict__ q,
                        const float* __restrict__ k,
                        const float* __restrict__ v,
                        const float* __restrict__ eigs,
                        float* __restrict__ out, int n_nodes) {
    __shared__ float s_pexp[PTYPES];
    if (threadIdx.x < PTYPES) s_pexp[threadIdx.x] = g_pexp[threadIdx.x];
    __syncthreads();

    int warp = (blockIdx.x * blockDim.x + threadIdx.x) >> 5;
    int lane = threadIdx.x & 31;
    if (warp >= n_nodes) return;
    const int row = warp;
    const int beg = g_rowptr[row];
    const int end = g_rowptr[row + 1];

    float4 acc0 = make_float4(0.f, 0.f, 0.f, 0.f);  // sum e0_j * v_j
    float4 acc1 = make_float4(0.f, 0.f, 0.f, 0.f);  // sum pw_j * v_j
    float  d0 = 0.f, d1 = 0.f;

    if (beg < end) {
        const float inv_sqrt_h = 0.08838834764831845f;  // 1/sqrt(128)
        const float expl = g_expl;
        float4 qv = __ldg(reinterpret_cast<const float4*>(q + (size_t)row * HDIM) + lane);
        // pre-scale q by 1/sqrt(H): per-lane z = qs.k + expl*(er.ec)
        qv.x *= inv_sqrt_h; qv.y *= inv_sqrt_h;
        qv.z *= inv_sqrt_h; qv.w *= inv_sqrt_h;
        float er = (lane < EDIM) ? expl * __ldg(eigs + (size_t)row * EDIM + lane) : 0.f;

        int j = beg;
        for (; j + 2 <= end; j += 2) {
            int p0 = __ldg(g_col_s + j);
            int p1 = __ldg(g_col_s + j + 1);
            int c0 = p0 & 0xFFFFFF, pt0 = ((unsigned)p0) >> 24;
            int c1 = p1 & 0xFFFFFF, pt1 = ((unsigned)p1) >> 24;

            float4 k0 = __ldg(reinterpret_cast<const float4*>(k + (size_t)c0 * HDIM) + lane);
            float4 k1 = __ldg(reinterpret_cast<const float4*>(k + (size_t)c1 * HDIM) + lane);
            float4 v0 = __ldg(reinterpret_cast<const float4*>(v + (size_t)c0 * HDIM) + lane);
            float4 v1 = __ldg(reinterpret_cast<const float4*>(v + (size_t)c1 * HDIM) + lane);
            float ec0 = (lane < EDIM) ? __ldg(eigs + (size_t)c0 * EDIM + lane) : 0.f;
            float ec1 = (lane < EDIM) ? __ldg(eigs + (size_t)c1 * EDIM + lane) : 0.f;

            float z0 = qv.x * k0.x + qv.y * k0.y + qv.z * k0.z + qv.w * k0.w + er * ec0;
            float z1 = qv.x * k1.x + qv.y * k1.y + qv.z * k1.z + qv.w * k1.w + er * ec1;
            #pragma unroll
            for (int o = 16; o > 0; o >>= 1) {
                z0 += __shfl_xor_sync(0xffffffffu, z0, o);
                z1 += __shfl_xor_sync(0xffffffffu, z1, o);
            }
            float e0 = expf(z0);
            float e1 = expf(z1);
            float pw0 = s_pexp[pt0];
            float pw1 = s_pexp[pt1];
            d0 += e0 + e1;
            d1 += pw0 + pw1;
            acc0.x += e0 * v0.x + e1 * v1.x;
            acc0.y += e0 * v0.y + e1 * v1.y;
            acc0.z += e0 * v0.z + e1 * v1.z;
            acc0.w += e0 * v0.w + e1 * v1.w;
            acc1.x += pw0 * v0.x + pw1 * v1.x;
            acc1.y += pw0 * v0.y + pw1 * v1.y;
            acc1.z += pw0 * v0.z + pw1 * v1.z;
            acc1.w += pw0 * v0.w + pw1 * v1.w;
        }
        if (j < end) {
            int p0 = __ldg(g_col_s + j);
            int c0 = p0 & 0xFFFFFF, pt0 = ((unsigned)p0) >> 24;
            float4 k0 = __ldg(reinterpret_cast<const float4*>(k + (size_t)c0 * HDIM) + lane);
            float4 v0 = __ldg(reinterpret_cast<const float4*>(v + (size_t)c0 * HDIM) + lane);
            float ec0 = (lane < EDIM) ? __ldg(eigs + (size_t)c0 * EDIM + lane) : 0.f;
            float z0 = qv.x * k0.x + qv.y * k0.y + qv.z * k0.z + qv.w * k0.w + er * ec0;
            #pragma unroll
            for (int o = 16; o > 0; o >>= 1)
                z0 += __shfl_xor_sync(0xffffffffu, z0, o);
            float e0 = expf(z0);
            float pw0 = s_pexp[pt0];
            d0 += e0;
            d1 += pw0;
            acc0.x += e0 * v0.x; acc0.y += e0 * v0.y;
            acc0.z += e0 * v0.z; acc0.w += e0 * v0.w;
            acc1.x += pw0 * v0.x; acc1.y += pw0 * v0.y;
            acc1.z += pw0 * v0.z; acc1.w += pw0 * v0.w;
        }

        float i0 = 0.5f / d0;
        float i1 = 0.5f / d1;
        acc0.x = i0 * acc0.x + i1 * acc1.x;
        acc0.y = i0 * acc0.y + i1 * acc1.y;
        acc0.z = i0 * acc0.z + i1 * acc1.z;
        acc0.w = i0 * acc0.w + i1 * acc1.w;
    }
    reinterpret_cast<float4*>(out + (size_t)row * HDIM)[lane] = acc0;
}

// ---------------------------------------------------------------------------
extern "C" void kernel_launch(void* const* d_in, const int* in_sizes, int n_in,
                              void* d_out, int out_size) {
    const float* q       = (const float*)d_in[0];
    const float* k       = (const float*)d_in[1];
    const float* v       = (const float*)d_in[2];
    const float* eigs    = (const float*)d_in[3];
    const float* lambda0 = (const float*)d_in[4];
    const float* path_w  = (const float*)d_in[5];
    const int*   indices = (const int*)d_in[6];
    const int*   ptype   = (const int*)d_in[7];
    float*       out     = (float*)d_out;

    int n_edges = in_sizes[6] / 2;
    int n_nodes = in_sizes[0] / HDIM;
    if (n_edges > EDGES)  n_edges = EDGES;
    if (n_nodes > NNODES) n_nodes = NNODES;

    int eb = (n_edges + 255) / 256;
    int rb = (n_nodes * 32 + 255) / 256;

    k_init<<<512, 256>>>(lambda0, path_w, n_nodes);
    k_hist<<<eb, 256>>>(indices, n_edges);
    k_scan<<<1, 1024>>>(n_nodes);
    k_scatter<<<eb, 256>>>(indices, ptype, n_edges);
    k_fused<<<rb, 256>>>(q, k, v, eigs, out, n_nodes);
}

// round 4
// speedup vs baseline: 2.2404x; 1.0231x over previous
#include <cuda_runtime.h>
#include <cuda_fp16.h>
#include <math.h>

#define NNODES 100000
#define EDGES  3200000
#define HDIM   128
#define EDIM   16
#define PTYPES 6

// ---- __device__ scratch (allocations are banned) ----
__device__ int    g_cnt[NNODES];        // degree histogram
__device__ int    g_rowptr[NNODES + 1]; // CSR row pointers
__device__ int    g_rowpos[NNODES];     // scatter cursors
__device__ int    g_col_s[EDGES];       // CSR-ordered packed (col | ptype<<24)
__device__ __half g_kh[NNODES * HDIM];  // fp16 copy of k   (25.6 MB)
__device__ __half g_eh[NNODES * EDIM];  // fp16 copy of eigs (3.2 MB)
__device__ float  g_pexp[PTYPES];       // exp(path_emb_w[p])
__device__ float  g_expl;               // exp(lambda0)

// ---------------------------------------------------------------------------
// 0) prep: zero histogram, exp tables, fp16 side-copies of k and eigs
// ---------------------------------------------------------------------------
__global__ void k_prep(const float* __restrict__ k,
                       const float* __restrict__ eigs,
                       const float* __restrict__ lambda0,
                       const float* __restrict__ path_w, int n_nodes) {
    int tid = blockIdx.x * blockDim.x + threadIdx.x;
    int stride = gridDim.x * blockDim.x;

    for (int i = tid; i < n_nodes; i += stride) g_cnt[i] = 0;

    // k -> fp16 (vector: float4 in, 4 halfs = uint2 out)
    int nk4 = n_nodes * (HDIM / 4);
    for (int i = tid; i < nk4; i += stride) {
        float4 f = __ldg(reinterpret_cast<const float4*>(k) + i);
        __half2 lo = __floats2half2_rn(f.x, f.y);
        __half2 hi = __floats2half2_rn(f.z, f.w);
        uint2 o;
        o.x = *reinterpret_cast<unsigned*>(&lo);
        o.y = *reinterpret_cast<unsigned*>(&hi);
        reinterpret_cast<uint2*>(g_kh)[i] = o;
    }
    // eigs -> fp16
    int ne4 = n_nodes * (EDIM / 4);
    for (int i = tid; i < ne4; i += stride) {
        float4 f = __ldg(reinterpret_cast<const float4*>(eigs) + i);
        __half2 lo = __floats2half2_rn(f.x, f.y);
        __half2 hi = __floats2half2_rn(f.z, f.w);
        uint2 o;
        o.x = *reinterpret_cast<unsigned*>(&lo);
        o.y = *reinterpret_cast<unsigned*>(&hi);
        reinterpret_cast<uint2*>(g_eh)[i] = o;
    }

    if (tid < PTYPES) g_pexp[tid] = expf(path_w[tid]);
    if (tid == 0)     g_expl = expf(lambda0[0]);
}

// ---------------------------------------------------------------------------
// 1) histogram of destination rows — 4 edges/thread, vectorized load
// ---------------------------------------------------------------------------
__global__ void k_hist(const int* __restrict__ indices, int n_edges) {
    int t = blockIdx.x * blockDim.x + threadIdx.x;
    int base = t * 4;
    if (base + 4 <= n_edges) {
        int4 r = __ldg(reinterpret_cast<const int4*>(indices) + t);
        atomicAdd(&g_cnt[r.x], 1);
        atomicAdd(&g_cnt[r.y], 1);
        atomicAdd(&g_cnt[r.z], 1);
        atomicAdd(&g_cnt[r.w], 1);
    } else {
        for (int e = base; e < n_edges; e++)
            atomicAdd(&g_cnt[__ldg(indices + e)], 1);
    }
}

// ---------------------------------------------------------------------------
// 2) exclusive scan (single block)
// ---------------------------------------------------------------------------
__global__ void k_scan(int n) {
    __shared__ int part[1024];
    int tid = threadIdx.x;
    int chunk = (n + 1023) / 1024;
    int start = tid * chunk;
    int end   = min(start + chunk, n);
    int s = 0;
    for (int i = start; i < end; i++) s += g_cnt[i];
    part[tid] = s;
    __syncthreads();
    for (int off = 1; off < 1024; off <<= 1) {
        int v = 0;
        if (tid >= off) v = part[tid - off];
        __syncthreads();
        if (tid >= off) part[tid] += v;
        __syncthreads();
    }
    int run = (tid == 0) ? 0 : part[tid - 1];
    for (int i = start; i < end; i++) {
        g_rowptr[i] = run;
        g_rowpos[i] = run;
        run += g_cnt[i];
    }
    if (end == n && start <= n) g_rowptr[n] = run;
}

// ---------------------------------------------------------------------------
// 3) scatter — 4 edges/thread, single packed 4B write per edge
// ---------------------------------------------------------------------------
__global__ void k_scatter(const int* __restrict__ indices,
                          const int* __restrict__ ptype, int n_edges) {
    int t = blockIdx.x * blockDim.x + threadIdx.x;
    int base = t * 4;
    if (base + 4 <= n_edges) {
        int4 r = __ldg(reinterpret_cast<const int4*>(indices) + t);
        int4 c = __ldg(reinterpret_cast<const int4*>(indices + n_edges) + t);
        int4 p = __ldg(reinterpret_cast<const int4*>(ptype) + t);
        int pos;
        pos = atomicAdd(&g_rowpos[r.x], 1); g_col_s[pos] = c.x | (p.x << 24);
        pos = atomicAdd(&g_rowpos[r.y], 1); g_col_s[pos] = c.y | (p.y << 24);
        pos = atomicAdd(&g_rowpos[r.z], 1); g_col_s[pos] = c.z | (p.z << 24);
        pos = atomicAdd(&g_rowpos[r.w], 1); g_col_s[pos] = c.w | (p.w << 24);
    } else {
        for (int e = base; e < n_edges; e++) {
            int row = __ldg(indices + e);
            int col = __ldg(indices + n_edges + e);
            int pt  = __ldg(ptype + e);
            int pos = atomicAdd(&g_rowpos[row], 1);
            g_col_s[pos] = col | (pt << 24);
        }
    }
}

// ---------------------------------------------------------------------------
// 4) fused pass: warp per row, single sweep.
//    out[row] = (0.5/d0) * sum_j e0_j v_j + (0.5/d1) * sum_j pw_j v_j
//    Scores from fp16 k/eigs; v and accumulation in fp32.
// ---------------------------------------------------------------------------
__global__ void __launch_bounds__(256)
k_fused(const float* __restrict__ q,
        const float* __restrict__ v,
        float* __restrict__ out, int n_nodes) {
    __shared__ float s_pexp[PTYPES];
    if (threadIdx.x < PTYPES) s_pexp[threadIdx.x] = g_pexp[threadIdx.x];
    __syncthreads();

    int warp = (blockIdx.x * blockDim.x + threadIdx.x) >> 5;
    int lane = threadIdx.x & 31;
    if (warp >= n_nodes) return;
    const int row = warp;
    const int beg = g_rowptr[row];
    const int end = g_rowptr[row + 1];

    float4 acc0 = make_float4(0.f, 0.f, 0.f, 0.f);  // sum e0_j * v_j
    float4 acc1 = make_float4(0.f, 0.f, 0.f, 0.f);  // sum pw_j * v_j
    float  d0 = 0.f, d1 = 0.f;

    if (beg < end) {
        const float inv_sqrt_h = 0.08838834764831845f;  // 1/sqrt(128)
        const float expl = g_expl;
        float4 qv = __ldg(reinterpret_cast<const float4*>(q + (size_t)row * HDIM) + lane);
        qv.x *= inv_sqrt_h; qv.y *= inv_sqrt_h;
        qv.z *= inv_sqrt_h; qv.w *= inv_sqrt_h;
        float er = (lane < EDIM)
                 ? expl * __half2float(g_eh[(size_t)row * EDIM + lane]) : 0.f;

        int j = beg;
        for (; j + 4 <= end; j += 4) {
            int   cc[4], pt[4];
            uint2 kr[4];
            float4 vr[4];
            float ec[4];
            #pragma unroll
            for (int u = 0; u < 4; u++) {
                int p = __ldg(g_col_s + j + u);
                cc[u] = p & 0xFFFFFF;
                pt[u] = ((unsigned)p) >> 24;
            }
            #pragma unroll
            for (int u = 0; u < 4; u++) {
                kr[u] = __ldg(reinterpret_cast<const uint2*>(g_kh + (size_t)cc[u] * HDIM) + lane);
                vr[u] = __ldg(reinterpret_cast<const float4*>(v + (size_t)cc[u] * HDIM) + lane);
                ec[u] = (lane < EDIM)
                      ? __half2float(__ldg(g_eh + (size_t)cc[u] * EDIM + lane)) : 0.f;
            }
            float z[4];
            #pragma unroll
            for (int u = 0; u < 4; u++) {
                float2 k01 = __half22float2(*reinterpret_cast<__half2*>(&kr[u].x));
                float2 k23 = __half22float2(*reinterpret_cast<__half2*>(&kr[u].y));
                z[u] = qv.x * k01.x + qv.y * k01.y
                     + qv.z * k23.x + qv.w * k23.y + er * ec[u];
            }
            #pragma unroll
            for (int o = 16; o > 0; o >>= 1) {
                #pragma unroll
                for (int u = 0; u < 4; u++)
                    z[u] += __shfl_xor_sync(0xffffffffu, z[u], o);
            }
            #pragma unroll
            for (int u = 0; u < 4; u++) {
                float e0 = __expf(z[u]);
                float pw = s_pexp[pt[u]];
                d0 += e0;
                d1 += pw;
                acc0.x += e0 * vr[u].x; acc0.y += e0 * vr[u].y;
                acc0.z += e0 * vr[u].z; acc0.w += e0 * vr[u].w;
                acc1.x += pw * vr[u].x; acc1.y += pw * vr[u].y;
                acc1.z += pw * vr[u].z; acc1.w += pw * vr[u].w;
            }
        }
        for (; j < end; j++) {
            int p  = __ldg(g_col_s + j);
            int c0 = p & 0xFFFFFF, pt0 = ((unsigned)p) >> 24;
            uint2 kr = __ldg(reinterpret_cast<const uint2*>(g_kh + (size_t)c0 * HDIM) + lane);
            float4 v0 = __ldg(reinterpret_cast<const float4*>(v + (size_t)c0 * HDIM) + lane);
            float ec0 = (lane < EDIM)
                      ? __half2float(__ldg(g_eh + (size_t)c0 * EDIM + lane)) : 0.f;
            float2 k01 = __half22float2(*reinterpret_cast<__half2*>(&kr.x));
            float2 k23 = __half22float2(*reinterpret_cast<__half2*>(&kr.y));
            float z0 = qv.x * k01.x + qv.y * k01.y
                     + qv.z * k23.x + qv.w * k23.y + er * ec0;
            #pragma unroll
            for (int o = 16; o > 0; o >>= 1)
                z0 += __shfl_xor_sync(0xffffffffu, z0, o);
            float e0 = __expf(z0);
            float pw = s_pexp[pt0];
            d0 += e0;
            d1 += pw;
            acc0.x += e0 * v0.x; acc0.y += e0 * v0.y;
            acc0.z += e0 * v0.z; acc0.w += e0 * v0.w;
            acc1.x += pw * v0.x; acc1.y += pw * v0.y;
            acc1.z += pw * v0.z; acc1.w += pw * v0.w;
        }

        float i0 = 0.5f / d0;
        float i1 = 0.5f / d1;
        acc0.x = i0 * acc0.x + i1 * acc1.x;
        acc0.y = i0 * acc0.y + i1 * acc1.y;
        acc0.z = i0 * acc0.z + i1 * acc1.z;
        acc0.w = i0 * acc0.w + i1 * acc1.w;
    }
    reinterpret_cast<float4*>(out + (size_t)row * HDIM)[lane] = acc0;
}

// ---------------------------------------------------------------------------
extern "C" void kernel_launch(void* const* d_in, const int* in_sizes, int n_in,
                              void* d_out, int out_size) {
    const float* q       = (const float*)d_in[0];
    const float* k       = (const float*)d_in[1];
    const float* v       = (const float*)d_in[2];
    const float* eigs    = (const float*)d_in[3];
    const float* lambda0 = (const float*)d_in[4];
    const float* path_w  = (const float*)d_in[5];
    const int*   indices = (const int*)d_in[6];
    const int*   ptype   = (const int*)d_in[7];
    float*       out     = (float*)d_out;

    int n_edges = in_sizes[6] / 2;
    int n_nodes = in_sizes[0] / HDIM;
    if (n_edges > EDGES)  n_edges = EDGES;
    if (n_nodes > NNODES) n_nodes = NNODES;

    int eb4 = (n_edges / 4 + 255) / 256 + 1;
    int rb  = (n_nodes * 32 + 255) / 256;

    k_prep<<<2048, 256>>>(k, eigs, lambda0, path_w, n_nodes);
    k_hist<<<eb4, 256>>>(indices, n_edges);
    k_scan<<<1, 1024>>>(n_nodes);
    k_scatter<<<eb4, 256>>>(indices, ptype, n_edges);
    k_fused<<<rb, 256>>>(q, v, out, n_nodes);
}